// round 13
// baseline (speedup 1.0000x reference)
#include <cuda_runtime.h>

#define NN    384
#define TS    32
#define NT    (NN / TS)       // 12
#define NBLK  (NT * NT)       // 144 < 148 SMs -> co-resident grid barrier safe
#define APITCH 36             // A smem row pitch (floats)
#define BPITCH 68             // dup'd B smem row pitch (floats)
#define CHUNK  24             // k rows per warp sub-chunk
#define WBUF   (CHUNK * APITCH + CHUNK * BPITCH)   // 2496 floats per warp
#define SMEM_BYTES (16 * WBUF * 4)                 // 159744 B
#define REDP   34             // reduction tile pitch
#define TILEOFF (16 * 1088)   // transpose-tile offset (floats) = past RED region
#define TPITCH 33

typedef unsigned long long ull;

// Scratch (device globals: no allocation allowed)
__device__ __align__(16) float g_u [NN * NN];
__device__ __align__(16) float g_uT[NN * NN];   // u transposed
__device__ __align__(16) float g_W [NN * NN];
__device__ __align__(16) float g_WT[NN * NN];   // W transposed

// Distributed grid barrier: per-block flags + one release word (monotone epochs)
__device__ unsigned g_flags[NBLK];
__device__ unsigned g_gen;

__device__ __forceinline__ void grid_barrier(unsigned epoch) {
    __syncthreads();
    if (blockIdx.x == 0) {
        int t = threadIdx.x;
        if (t >= 1 && t < NBLK) {
            while (*(volatile unsigned*)&g_flags[t] < epoch) { }
        }
        __syncthreads();
        if (t == 0) {
            __threadfence();
            *(volatile unsigned*)&g_gen = epoch;
        }
    } else {
        if (threadIdx.x == 0) {
            __threadfence();
            *(volatile unsigned*)&g_flags[blockIdx.x] = epoch;
            while (*(volatile unsigned*)&g_gen < epoch) { }
        }
    }
    __syncthreads();
    __threadfence();
}

__device__ __forceinline__ float decode_lam(const void* p) {
    int raw = *(const int*)p;
    unsigned ub = (unsigned)raw;
    if (ub < 0x01000000u) return (float)raw;   // small-int bits (int32/int64 low)
    return __int_as_float(raw);                // float32 bits
}

// Packed fp32x2 (not emitted by ptxas from C++)
__device__ __forceinline__ void ffma2(ull& d, ull a, ull b) {
    asm("fma.rn.f32x2 %0, %1, %2, %0;" : "+l"(d) : "l"(a), "l"(b));
}
__device__ __forceinline__ void fadd2(ull& d, ull a) {
    asm("add.rn.f32x2 %0, %0, %1;" : "+l"(d) : "l"(a));
}
__device__ __forceinline__ float2 upk(ull v) {
    float2 f; asm("mov.b64 {%0, %1}, %2;" : "=f"(f.x), "=f"(f.y) : "l"(v)); return f;
}

extern __shared__ float smem[];

// Stage CHUNK k-rows, natural+coalesced, into warp-private buffers.
// wA[k][c] = srcA[(aRow0+k)*NN + aCol0 + c]            (32 cols)
// wB[k][2c], wB[k][2c+1] = srcB[(bRow0+k)*NN + bCol0+c] (duplicated pairs)
__device__ __forceinline__ void stage_chunk(float* wA, float* wB,
                                            const float* __restrict__ srcA,
                                            int aRow0, int aCol0,
                                            const float* __restrict__ srcB,
                                            int bRow0, int bCol0, int lane) {
    int kk = lane >> 3;          // 0..3
    int c4 = 4 * (lane & 7);     // 0,4..28
#pragma unroll
    for (int j = 0; j < 6; ++j) {
        int k = 4 * j + kk;
        float4 va = *(const float4*)&srcA[(aRow0 + k) * NN + aCol0 + c4];
        float4 vb = *(const float4*)&srcB[(bRow0 + k) * NN + bCol0 + c4];
        *(float4*)&wA[k * APITCH + c4] = va;
        *(float4*)&wB[k * BPITCH + 2 * c4]     = make_float4(vb.x, vb.x, vb.y, vb.y);
        *(float4*)&wB[k * BPITCH + 2 * c4 + 4] = make_float4(vb.z, vb.z, vb.w, vb.w);
    }
}

// k-loop over one staged chunk: 8x4 micro-tile, pair-packed FFMA2.
__device__ __forceinline__ void kloop(const float* wA, const float* wB,
                                      int ty, int tx, ull acc[4][4]) {
#pragma unroll 4
    for (int k = 0; k < CHUNK; ++k) {
        const float* pa = wA + k * APITCH + 8 * ty;
        ulonglong2 aLo = *(const ulonglong2*)pa;         // rows (0,1),(2,3)
        ulonglong2 aHi = *(const ulonglong2*)(pa + 4);   // rows (4,5),(6,7)
        const float* pb = wB + k * BPITCH + 8 * tx;
        ulonglong2 b01 = *(const ulonglong2*)pb;         // (b0,b0),(b1,b1)
        ulonglong2 b23 = *(const ulonglong2*)(pb + 4);   // (b2,b2),(b3,b3)
        ffma2(acc[0][0], aLo.x, b01.x); ffma2(acc[1][0], aLo.y, b01.x);
        ffma2(acc[2][0], aHi.x, b01.x); ffma2(acc[3][0], aHi.y, b01.x);
        ffma2(acc[0][1], aLo.x, b01.y); ffma2(acc[1][1], aLo.y, b01.y);
        ffma2(acc[2][1], aHi.x, b01.y); ffma2(acc[3][1], aHi.y, b01.y);
        ffma2(acc[0][2], aLo.x, b23.x); ffma2(acc[1][2], aLo.y, b23.x);
        ffma2(acc[2][2], aHi.x, b23.x); ffma2(acc[3][2], aHi.y, b23.x);
        ffma2(acc[0][3], aLo.x, b23.y); ffma2(acc[1][3], aLo.y, b23.y);
        ffma2(acc[2][3], aHi.x, b23.y); ffma2(acc[3][3], aHi.y, b23.y);
    }
}

// Store partials + pairwise reduce over 16 warps; returns packed (r0,r1) sum
// for output rows (2*ri, 2*ri+1), col cj.
__device__ __forceinline__ ull reduce_partials(float* red, ull acc[4][4],
                                               int w, int ty, int tx,
                                               int cj, int ri) {
    __syncthreads();                                   // all k-loops done
#pragma unroll
    for (int rp = 0; rp < 4; ++rp)
#pragma unroll
        for (int c = 0; c < 4; ++c)
            *(ull*)&red[w * 1088 + (4 * tx + c) * REDP + 8 * ty + 2 * rp] = acc[rp][c];
    __syncthreads();
    ull s = *(const ull*)&red[cj * REDP + 2 * ri];
#pragma unroll
    for (int w2 = 1; w2 < 16; ++w2)
        fadd2(s, *(const ull*)&red[w2 * 1088 + cj * REDP + 2 * ri]);
    return s;
}

__global__ __launch_bounds__(512, 1)
void fused_kernel(const float* __restrict__ od,
                  const int*   __restrict__ adj,
                  const float* __restrict__ dist,
                  const void*  __restrict__ lam_p,
                  float*       __restrict__ out) {
    const int tid  = threadIdx.x;
    const int w    = tid >> 5;
    const int lane = tid & 31;
    const int ty   = lane >> 3;            // rows 8ty..8ty+7
    const int tx   = lane & 7;             // cols 4tx..4tx+3
    const int tileX = blockIdx.x % NT;
    const int tileY = blockIdx.x / NT;
    const int rowBlk = tileY * TS;
    const int colBlk = tileX * TS;
    const int cj = tid >> 4;               // epilogue col 0..31
    const int ri = tid & 15;               // epilogue row-pair 0..15
    const int er  = tid >> 4;              // final-store row 0..31
    const int ec0 = 2 * (tid & 15);        // final-store col pair

    float* wA   = smem + w * WBUF;
    float* wB   = wA + CHUNK * APITCH;
    float* red  = smem;                    // 16x1088 fl (reused after sync)
    float* tile = smem + TILEOFF;          // 32x33 transpose tile

    const unsigned base = *(volatile unsigned*)&g_gen;

    // ---------------- Phase 1: build u and u^T ------------------------------
    {
        const float lam = decode_lam(lam_p);
        int rr = rowBlk + er;
        int cc = colBlk + ec0;
        int idx = rr * NN + cc;
        int2   a2 = *(const int2*)&adj[idx];
        float2 d2 = *(const float2*)&dist[idx];
        float2 v;
        v.x = (a2.x > 0 && rr != cc    ) ? expf(-lam * d2.x) : 0.f;
        v.y = (a2.y > 0 && rr != cc + 1) ? expf(-lam * d2.y) : 0.f;
        *(float2*)&g_u[idx] = v;
        tile[er * TPITCH + ec0]     = v.x;
        tile[er * TPITCH + ec0 + 1] = v.y;
        __syncthreads();
        float t0 = tile[(2 * ri)     * TPITCH + cj];
        float t1 = tile[(2 * ri + 1) * TPITCH + cj];
        *(float2*)&g_uT[(colBlk + cj) * NN + rowBlk + 2 * ri] = make_float2(t0, t1);
    }
    grid_barrier(base + 1);

    // ---------------- Phase 2: G = u@u; W = od/S epilogue -------------------
    {
        ull acc[4][4];
#pragma unroll
        for (int i = 0; i < 4; ++i)
#pragma unroll
            for (int j = 0; j < 4; ++j) acc[i][j] = 0ull;

        int kb = w * CHUNK;                // warp-private K slice [kb, kb+24)
        // A^T[k][r] = u[rowBlk+r][k] = g_uT[k][rowBlk+r]; B[k][c] = g_u[k][colBlk+c]
        stage_chunk(wA, wB, g_uT, kb, rowBlk, g_u, kb, colBlk, lane);
        __syncwarp();
        kloop(wA, wB, ty, tx, acc);

        ull s = reduce_partials(red, acc, w, ty, tx, cj, ri);
        float2 sf = upk(s);
        {
            int r0 = rowBlk + 2 * ri;
            int c  = colBlk + cj;
            float2 uv = *(const float2*)&g_uT[c * NN + r0];       // u[r0][c], u[r1][c]
            float od0 = od[r0 * NN + c];
            float od1 = od[(r0 + 1) * NN + c];
            float S0 = uv.x + ((r0 != c)     ? sf.x : 0.f);
            float S1 = uv.y + ((r0 + 1 != c) ? sf.y : 0.f);
            float W0 = (od0 > 0.f && r0 != c     && S0 > 0.f) ? (od0 / S0) : 0.f;
            float W1 = (od1 > 0.f && r0 + 1 != c && S1 > 0.f) ? (od1 / S1) : 0.f;
            *(float2*)&g_WT[c * NN + r0] = make_float2(W0, W1);   // coalesced W^T
            tile[(2 * ri) * TPITCH + cj]     = W0;                // natural via bounce
            tile[(2 * ri + 1) * TPITCH + cj] = W1;
        }
        __syncthreads();
        {
            float v0 = tile[er * TPITCH + ec0];
            float v1 = tile[er * TPITCH + ec0 + 1];
            *(float2*)&g_W[(rowBlk + er) * NN + colBlk + ec0] = make_float2(v0, v1);
        }
    }
    grid_barrier(base + 2);

    // ---------------- Phase 3: C = [W | u^T] @ [u^T ; W]; out epilogue ------
    {
        ull acc[4][4];
#pragma unroll
        for (int i = 0; i < 4; ++i)
#pragma unroll
            for (int j = 0; j < 4; ++j) acc[i][j] = 0ull;

        // virtual K in [0,768): warp w owns [48w, 48w+48) -> 2 chunks of 24.
        // w < 8  : k < 384:  A'[k][r] = W[rowBlk+r][k] = g_WT[k][rowBlk+r]
        //                    B'[k][c] = u[colBlk+c][k] = g_uT[k][colBlk+c]
        // w >= 8 : k' = k-384: A'[k][r] = u[k'][rowBlk+r] = g_u[k'][..]
        //                    B'[k][c] = W[k'][colBlk+c] = g_W[k'][..]
        const float* srcA = (w < 8) ? g_WT : g_u;
        const float* srcB = (w < 8) ? g_uT : g_W;
        int kb = (w < 8) ? (48 * w) : (48 * w - 384);

        stage_chunk(wA, wB, srcA, kb, rowBlk, srcB, kb, colBlk, lane);
        __syncwarp();
        kloop(wA, wB, ty, tx, acc);
        __syncwarp();
        stage_chunk(wA, wB, srcA, kb + CHUNK, rowBlk, srcB, kb + CHUNK, colBlk, lane);
        __syncwarp();
        kloop(wA, wB, ty, tx, acc);

        ull s = reduce_partials(red, acc, w, ty, tx, cj, ri);
        float2 sf = upk(s);
        {
            int r0 = rowBlk + 2 * ri;
            int c  = colBlk + cj;
            float2 uv = *(const float2*)&g_uT[c * NN + r0];
            float2 wv = *(const float2*)&g_WT[c * NN + r0];
            float o0 = uv.x * (wv.x + sf.x);
            float o1 = uv.y * (wv.y + sf.y);
            tile[(2 * ri) * TPITCH + cj]     = o0;
            tile[(2 * ri + 1) * TPITCH + cj] = o1;
        }
        __syncthreads();
        {
            float v0 = tile[er * TPITCH + ec0];
            float v1 = tile[er * TPITCH + ec0 + 1];
            *(float2*)&out[(rowBlk + er) * NN + colBlk + ec0] = make_float2(v0, v1);
        }
    }
}

extern "C" void kernel_launch(void* const* d_in, const int* in_sizes, int n_in,
                              void* d_out, int out_size) {
    const float* od   = (const float*)d_in[0];
    const int*   adj  = (const int*)d_in[1];
    const float* dist = (const float*)d_in[2];
    const void*  lamp = d_in[3];
    float* out = (float*)d_out;

    cudaFuncSetAttribute(fused_kernel,
                         cudaFuncAttributeMaxDynamicSharedMemorySize, SMEM_BYTES);
    fused_kernel<<<NBLK, 512, SMEM_BYTES>>>(od, adj, dist, lamp, out);
}